// round 16
// baseline (speedup 1.0000x reference)
#include <cuda_runtime.h>
#include <cuda_fp16.h>
#include <math.h>
#include <stdint.h>

// Problem constants (fixed by the dataset)
#define T_TOK 2048
#define DIM   2048
#define NE    8
#define NI    2048
#define CAP   2048
#define SOFTCAP 30.0f

// ---------------- device scratch (no runtime allocation) ----------------
__device__ __half g_xh [(size_t)T_TOK * DIM];
__device__ __half g_w1h[(size_t)NE * NI * DIM];
__device__ __half g_w3h[(size_t)NE * NI * DIM];
__device__ __half g_w2h[(size_t)NE * DIM * NI];
__device__ __half g_hh [(size_t)NE * CAP * NI];     // GLU hidden, fp16
__device__ int    g_sel_token[NE * CAP];
__device__ float  g_sel_w[NE * CAP];
__device__ int    g_count[NE];
__device__ int    g_topk_idx[T_TOK * 2];
__device__ float  g_topk_w[T_TOK * 2];

// ---------------- helpers ----------------
__device__ __forceinline__ float gelu_exact(float v) {
    return 0.5f * v * (1.0f + erff(v * 0.70710678118654752440f));
}
__device__ __forceinline__ uint32_t smem_u32(const void* p) {
    uint32_t a;
    asm("{ .reg .u64 t; cvta.to.shared.u64 t, %1; cvt.u32.u64 %0, t; }" : "=r"(a) : "l"(p));
    return a;
}
__device__ __forceinline__ void cp16(uint32_t dst, const void* src) {
    asm volatile("cp.async.cg.shared.global [%0], [%1], 16;" :: "r"(dst), "l"(src) : "memory");
}

// ---- mbarrier pipeline primitives (sm_90 generic) ----
__device__ __forceinline__ void mbar_init(uint32_t a, uint32_t cnt) {
    asm volatile("mbarrier.init.shared.b64 [%0], %1;" :: "r"(a), "r"(cnt) : "memory");
}
__device__ __forceinline__ void mbar_arrive(uint32_t a) {
    asm volatile("mbarrier.arrive.shared.b64 _, [%0];" :: "r"(a) : "memory");
}
// this thread's prior cp.asyncs arrive on mbar when complete (no count bump)
__device__ __forceinline__ void cp_arrive(uint32_t a) {
    asm volatile("cp.async.mbarrier.arrive.noinc.shared.b64 [%0];" :: "r"(a) : "memory");
}
__device__ __forceinline__ void mbar_wait(uint32_t a, uint32_t ph) {
    asm volatile(
        "{\n\t.reg .pred P;\n\t"
        "W%=:\n\t"
        "mbarrier.try_wait.parity.shared.b64 P, [%0], %1;\n\t"
        "@!P bra W%=;\n\t}"
        :: "r"(a), "r"(ph) : "memory");
}

#define LDSM4(r0, r1, r2, r3, addr) \
    asm volatile("ldmatrix.sync.aligned.m8n8.x4.shared.b16 {%0,%1,%2,%3}, [%4];" \
                 : "=r"(r0), "=r"(r1), "=r"(r2), "=r"(r3) : "r"(addr))

#define MMA4(c, a, b0, b1) \
    asm volatile("mma.sync.aligned.m16n8k16.row.col.f32.f16.f16.f32 " \
                 "{%0,%1,%2,%3}, {%4,%5,%6,%7}, {%8,%9}, {%0,%1,%2,%3};" \
                 : "+f"((c)[0]), "+f"((c)[1]), "+f"((c)[2]), "+f"((c)[3]) \
                 : "r"((a)[0]), "r"((a)[1]), "r"((a)[2]), "r"((a)[3]), \
                   "r"(b0), "r"(b1))

// vector fp32 atomic add (no return): 8B-aligned address required.
__device__ __forceinline__ void red_add_v2(float* p, float a, float b) {
    asm volatile("red.global.add.v2.f32 [%0], {%1, %2};" :: "l"(p), "f"(a), "f"(b) : "memory");
}

// smem tile geometry: rows of 32 halves (64B) + 16B pad -> 80B row stride.
// conflict-free for both cp.async writes and ldmatrix reads.
#define ROWB 80

// ------ 1) fused: fp32->fp16 weight converts (y=0..2) + router (y=3) ------
__global__ void prep_kernel(const float* __restrict__ s0, __half* __restrict__ d0,
                            const float* __restrict__ s1, __half* __restrict__ d1,
                            const float* __restrict__ s2, __half* __restrict__ d2,
                            long n4,
                            const float* __restrict__ x,
                            const float* __restrict__ wg,
                            float* __restrict__ out) {
    const int tid = threadIdx.x;
    if (blockIdx.y < 3) {
        const float* src = (blockIdx.y == 0) ? s0 : (blockIdx.y == 1) ? s1 : s2;
        __half*      dst = (blockIdx.y == 0) ? d0 : (blockIdx.y == 1) ? d1 : d2;
        long i = (long)blockIdx.x * 256 + tid;
        const long stride = (long)gridDim.x * 256;
        for (; i < n4; i += stride) {
            float4 v = ((const float4*)src)[i];
            __half2 h0 = __floats2half2_rn(v.x, v.y);
            __half2 h1 = __floats2half2_rn(v.z, v.w);
            uint2 o;
            o.x = *(uint32_t*)&h0;
            o.y = *(uint32_t*)&h1;
            ((uint2*)dst)[i] = o;
        }
        return;
    }
    // ---- router branch ----
    const int t = blockIdx.x;
    if (t >= T_TOK) return;
    const float4* xr4 = (const float4*)(x + (size_t)t * DIM);
    const float4* wg4 = (const float4*)wg;

    // zero this token's output row (atomic-accumulation target for mma2)
    float4* orow = (float4*)(out + (size_t)t * DIM);
#pragma unroll
    for (int q = tid; q < DIM / 4; q += 256)
        orow[q] = make_float4(0.f, 0.f, 0.f, 0.f);

    float acc[NE];
#pragma unroll
    for (int e = 0; e < NE; e++) acc[e] = 0.f;
#pragma unroll
    for (int q = tid; q < DIM / 4; q += 256) {      // 2 trips
        float4 xv = xr4[q];
        __half2 h0 = __floats2half2_rn(xv.x, xv.y);
        __half2 h1 = __floats2half2_rn(xv.z, xv.w);
        uint2 o; o.x = *(uint32_t*)&h0; o.y = *(uint32_t*)&h1;
        ((uint2*)(g_xh + (size_t)t * DIM))[q] = o;  // fused convert
#pragma unroll
        for (int e = 0; e < NE; e++) {
            float4 w = wg4[e * (DIM / 4) + q];
            acc[e] += xv.x * w.x + xv.y * w.y + xv.z * w.z + xv.w * w.w;
        }
    }

    __shared__ float sh[NE][256];
#pragma unroll
    for (int e = 0; e < NE; e++) sh[e][tid] = acc[e];
    __syncthreads();
    for (int s = 128; s > 0; s >>= 1) {
        if (tid < s) {
#pragma unroll
            for (int e = 0; e < NE; e++) sh[e][tid] += sh[e][tid + s];
        }
        __syncthreads();
    }

    if (tid == 0) {
        float l[NE];
        float mx = -1e30f;
#pragma unroll
        for (int e = 0; e < NE; e++) {
            l[e] = SOFTCAP * tanhf(sh[e][0] / SOFTCAP);
            mx = fmaxf(mx, l[e]);
        }
        float sum = 0.f;
#pragma unroll
        for (int e = 0; e < NE; e++) { l[e] = expf(l[e] - mx); sum += l[e]; }
        float inv = 1.f / sum;
        int i0 = 0;
#pragma unroll
        for (int e = 1; e < NE; e++) if (l[e] > l[i0]) i0 = e;
        int i1 = (i0 == 0) ? 1 : 0;
#pragma unroll
        for (int e = 0; e < NE; e++) {
            if (e == i0) continue;
            if (l[e] > l[i1]) i1 = e;
        }
        g_topk_idx[t * 2 + 0] = i0; g_topk_w[t * 2 + 0] = l[i0] * inv;
        g_topk_idx[t * 2 + 1] = i1; g_topk_w[t * 2 + 1] = l[i1] * inv;
    }
}

// ---------------- 2) Deterministic counting sort by expert ----------------
__global__ void sort_kernel() {
    const int wid  = threadIdx.x >> 5;
    const int lane = threadIdx.x & 31;
    if (wid >= NE) return;
    int running = 0;
    for (int base = 0; base < T_TOK * 2; base += 32) {
        const int s  = base + lane;
        const int ex = g_topk_idx[s];
        const bool p = (ex == wid);
        const unsigned m = __ballot_sync(0xffffffffu, p);
        if (p) {
            const int rank = running + __popc(m & ((1u << lane) - 1u));
            const int pos  = wid * CAP + rank;
            g_sel_token[pos] = s >> 1;
            g_sel_w[pos]     = g_topk_w[s];
        }
        running += __popc(m);
    }
    if (lane == 0) g_count[wid] = running;
}

// ---------------- 3) GEMM1: h = gelu(Xsel W1^T) * (Xsel W3^T) ----------------
// CTA 128(M) x 64(N), dual B. k-tile 32, 4-slot mbarrier ring pipeline:
// no __syncthreads in the mainloop — warps decoupled, skew absorbed up to
// one full iteration. full[s]: 256 cp-arrivals; empty[s]: 256 consumer arrivals.
#define STG1 20480   // A 128*80 + B1 64*80 + B3 64*80

__global__ __launch_bounds__(256) void mma1_kernel() {
    const int e    = blockIdx.y >> 4;
    const int mt   = blockIdx.y & 15;
    const int row0 = mt * 128;
    const int cnt  = g_count[e];
    if (row0 >= cnt) return;
    const int n0 = blockIdx.x * 64;

    extern __shared__ char dsm[];
    __shared__ int tok[128];
    __shared__ __align__(8) uint64_t s_full[4], s_empty[4];

    const int tid  = threadIdx.x;
    const int wid  = tid >> 5;
    const int lane = tid & 31;

    if (tid < 128) {
        const int r = row0 + tid;
        tok[tid] = (r < cnt) ? g_sel_token[e * CAP + r] : 0;
    }
    if (tid == 0) {
#pragma unroll
        for (int s = 0; s < 4; s++) {
            mbar_init(smem_u32(&s_full[s]),  256);
            mbar_init(smem_u32(&s_empty[s]), 256);
        }
    }
    __syncthreads();

    const uint32_t dyn0 = smem_u32(dsm);
    uint32_t fb[4], eb[4];
#pragma unroll
    for (int s = 0; s < 4; s++) { fb[s] = smem_u32(&s_full[s]); eb[s] = smem_u32(&s_empty[s]); }

    const int seg = tid & 3;        // k segment (8 halves)
    const int r64 = tid >> 2;       // 0..63
    const __half* a0src = g_xh  + (size_t)tok[r64]      * DIM + seg * 8;
    const __half* a1src = g_xh  + (size_t)tok[r64 + 64] * DIM + seg * 8;
    const __half* b1src = g_w1h + ((size_t)e * NI + n0 + r64) * DIM + seg * 8;
    const __half* b3src = g_w3h + ((size_t)e * NI + n0 + r64) * DIM + seg * 8;
    const uint32_t dA0 = (uint32_t)(r64 * ROWB + seg * 16);
    const uint32_t dA1 = (uint32_t)((r64 + 64) * ROWB + seg * 16);

    auto load_stage = [&](int s, int kb) {
        const uint32_t b = dyn0 + s * STG1;
        cp16(b + dA0, a0src + kb);
        cp16(b + dA1, a1src + kb);
        cp16(b + 10240 + dA0, b1src + kb);
        cp16(b + 15360 + dA0, b3src + kb);
        cp_arrive(fb[s]);
    };
    load_stage(0, 0); load_stage(1, 32); load_stage(2, 64);

    const int wm = wid & 1, wn = wid >> 1;
    float c1[4][2][4], c3[4][2][4];
#pragma unroll
    for (int mf = 0; mf < 4; mf++)
#pragma unroll
        for (int nf = 0; nf < 2; nf++)
#pragma unroll
            for (int k = 0; k < 4; k++) { c1[mf][nf][k] = 0.f; c3[mf][nf][k] = 0.f; }

    const uint32_t lrow = (uint32_t)((lane & 15) * ROWB + (lane >> 4) * 16);

    for (int i = 0; i < 64; i++) {
        const int s = i & 3;
        mbar_wait(fb[s], (i >> 2) & 1);            // stage i data ready (acquire)

        const uint32_t sb  = dyn0 + s * STG1;
        const uint32_t Ab  = sb + (uint32_t)(wm * 64 * ROWB) + lrow;
        const uint32_t B1b = sb + 10240 + (uint32_t)(wn * 16 * ROWB) + lrow;
        const uint32_t B3b = sb + 15360 + (uint32_t)(wn * 16 * ROWB) + lrow;
#pragma unroll
        for (int kk = 0; kk < 2; kk++) {
            uint32_t p1[4], p3[4];
            LDSM4(p1[0], p1[1], p1[2], p1[3], B1b + kk * 32);
            LDSM4(p3[0], p3[1], p3[2], p3[3], B3b + kk * 32);
#pragma unroll
            for (int mf = 0; mf < 4; mf++) {
                uint32_t a[4];
                LDSM4(a[0], a[1], a[2], a[3], Ab + mf * (16 * ROWB) + kk * 32);
                MMA4(c1[mf][0], a, p1[0], p1[2]);
                MMA4(c1[mf][1], a, p1[1], p1[3]);
                MMA4(c3[mf][0], a, p3[0], p3[2]);
                MMA4(c3[mf][1], a, p3[1], p3[3]);
            }
        }
        mbar_arrive(eb[s]);                        // this thread done reading stage i

        const int nx = i + 3;                      // prefetch tail
        if (nx < 64) {
            const int ns = nx & 3;
            if (nx >= 4) mbar_wait(eb[ns], ((nx >> 2) - 1) & 1);  // slot free
            load_stage(ns, nx * 32);
        }
    }

    // epilogue: h = gelu(a) * b -> fp16
#pragma unroll
    for (int mf = 0; mf < 4; mf++) {
        const int rb = row0 + wm * 64 + mf * 16 + (lane >> 2);
#pragma unroll
        for (int nf = 0; nf < 2; nf++) {
            const int col = n0 + wn * 16 + nf * 8 + (lane & 3) * 2;
            if (rb < cnt) {
                __half2 h = __floats2half2_rn(
                    gelu_exact(c1[mf][nf][0]) * c3[mf][nf][0],
                    gelu_exact(c1[mf][nf][1]) * c3[mf][nf][1]);
                *(__half2*)(g_hh + ((size_t)(e * CAP) + rb) * NI + col) = h;
            }
            if (rb + 8 < cnt) {
                __half2 h = __floats2half2_rn(
                    gelu_exact(c1[mf][nf][2]) * c3[mf][nf][2],
                    gelu_exact(c1[mf][nf][3]) * c3[mf][nf][3]);
                *(__half2*)(g_hh + ((size_t)(e * CAP) + rb + 8) * NI + col) = h;
            }
        }
    }
}

// ---------------- 4) GEMM2: out[token] += sel_w * (h W2^T) (vector RED) ---
// CTA 128(M) x 128(N). k-tile 32, same 4-slot mbarrier ring pipeline.
#define STG2 20480   // A 128*80 + B 128*80

__global__ __launch_bounds__(256) void mma2_kernel(float* __restrict__ out) {
    const int e    = blockIdx.y >> 4;
    const int mt   = blockIdx.y & 15;
    const int row0 = mt * 128;
    const int cnt  = g_count[e];
    if (row0 >= cnt) return;
    const int n0 = blockIdx.x * 128;

    extern __shared__ char dsm[];
    __shared__ int tok[128];
    __shared__ __align__(8) uint64_t s_full[4], s_empty[4];

    const int tid  = threadIdx.x;
    const int wid  = tid >> 5;
    const int lane = tid & 31;

    if (tid < 128) {
        const int r = row0 + tid;
        tok[tid] = (r < cnt) ? g_sel_token[e * CAP + r] : 0;
    }
    if (tid == 0) {
#pragma unroll
        for (int s = 0; s < 4; s++) {
            mbar_init(smem_u32(&s_full[s]),  256);
            mbar_init(smem_u32(&s_empty[s]), 256);
        }
    }
    __syncthreads();

    const uint32_t dyn0 = smem_u32(dsm);
    uint32_t fb[4], eb[4];
#pragma unroll
    for (int s = 0; s < 4; s++) { fb[s] = smem_u32(&s_full[s]); eb[s] = smem_u32(&s_empty[s]); }

    const int seg = tid & 3;
    const int r64 = tid >> 2;
    const __half* a0src = g_hh  + ((size_t)(e * CAP) + row0 + r64)      * NI + seg * 8;
    const __half* a1src = g_hh  + ((size_t)(e * CAP) + row0 + r64 + 64) * NI + seg * 8;
    const __half* b0src = g_w2h + ((size_t)e * DIM + n0 + r64)      * NI + seg * 8;
    const __half* b1src = g_w2h + ((size_t)e * DIM + n0 + r64 + 64) * NI + seg * 8;
    const uint32_t d0 = (uint32_t)(r64 * ROWB + seg * 16);
    const uint32_t d1 = (uint32_t)((r64 + 64) * ROWB + seg * 16);

    auto load_stage = [&](int s, int kb) {
        const uint32_t b = dyn0 + s * STG2;
        cp16(b + d0, a0src + kb);
        cp16(b + d1, a1src + kb);
        cp16(b + 10240 + d0, b0src + kb);
        cp16(b + 10240 + d1, b1src + kb);
        cp_arrive(fb[s]);
    };
    load_stage(0, 0); load_stage(1, 32); load_stage(2, 64);

    const int wm = wid & 1, wn = wid >> 1;
    float c[4][4][4];
#pragma unroll
    for (int mf = 0; mf < 4; mf++)
#pragma unroll
        for (int nf = 0; nf < 4; nf++)
#pragma unroll
            for (int k = 0; k < 4; k++) c[mf][nf][k] = 0.f;

    const uint32_t lrow = (uint32_t)((lane & 15) * ROWB + (lane >> 4) * 16);

    for (int i = 0; i < 64; i++) {
        const int s = i & 3;
        mbar_wait(fb[s], (i >> 2) & 1);

        const uint32_t sb = dyn0 + s * STG2;
        const uint32_t Ab = sb + (uint32_t)(wm * 64 * ROWB) + lrow;
        const uint32_t Bb = sb + 10240 + (uint32_t)(wn * 32 * ROWB) + lrow;
#pragma unroll
        for (int kk = 0; kk < 2; kk++) {
            uint32_t bb0[4], bb1v[4];
            LDSM4(bb0[0], bb0[1], bb0[2], bb0[3], Bb + kk * 32);
            LDSM4(bb1v[0], bb1v[1], bb1v[2], bb1v[3], Bb + 16 * ROWB + kk * 32);
#pragma unroll
            for (int mf = 0; mf < 4; mf++) {
                uint32_t a[4];
                LDSM4(a[0], a[1], a[2], a[3], Ab + mf * (16 * ROWB) + kk * 32);
                MMA4(c[mf][0], a, bb0[0], bb0[2]);
                MMA4(c[mf][1], a, bb0[1], bb0[3]);
                MMA4(c[mf][2], a, bb1v[0], bb1v[2]);
                MMA4(c[mf][3], a, bb1v[1], bb1v[3]);
            }
        }
        mbar_arrive(eb[s]);

        const int nx = i + 3;
        if (nx < 64) {
            const int ns = nx & 3;
            if (nx >= 4) mbar_wait(eb[ns], ((nx >> 2) - 1) & 1);
            load_stage(ns, nx * 32);
        }
    }

    // epilogue: scale by routing weight, vector-RED into out[token]
#pragma unroll
    for (int mf = 0; mf < 4; mf++) {
        const int rb = row0 + wm * 64 + mf * 16 + (lane >> 2);
        const float w0 = (rb < cnt)     ? g_sel_w[e * CAP + rb]     : 0.f;
        const float w1 = (rb + 8 < cnt) ? g_sel_w[e * CAP + rb + 8] : 0.f;
        const int t0 = tok[rb - row0 < 128 ? rb - row0 : 0];
        const int t1 = tok[(rb + 8 - row0) < 128 ? (rb + 8 - row0) : 0];
#pragma unroll
        for (int nf = 0; nf < 4; nf++) {
            const int col = n0 + wn * 32 + nf * 8 + (lane & 3) * 2;   // even -> 8B aligned
            if (rb < cnt)
                red_add_v2(out + (size_t)t0 * DIM + col,
                           c[mf][nf][0] * w0, c[mf][nf][1] * w0);
            if (rb + 8 < cnt)
                red_add_v2(out + (size_t)t1 * DIM + col,
                           c[mf][nf][2] * w1, c[mf][nf][3] * w1);
        }
    }
}

// ---------------- launch ----------------
extern "C" void kernel_launch(void* const* d_in, const int* in_sizes, int n_in,
                              void* d_out, int out_size) {
    const float* x      = (const float*)d_in[0];
    const float* w_gate = (const float*)d_in[1];
    const float* w1     = (const float*)d_in[2];
    const float* w3     = (const float*)d_in[3];
    const float* w2     = (const float*)d_in[4];
    float* out = (float*)d_out;
    (void)in_sizes; (void)n_in; (void)out_size;

    cudaFuncSetAttribute(mma1_kernel, cudaFuncAttributeMaxDynamicSharedMemorySize, 4 * STG1);
    cudaFuncSetAttribute(mma2_kernel, cudaFuncAttributeMaxDynamicSharedMemorySize, 4 * STG2);

    __half *w1h, *w3h, *w2h;
    cudaGetSymbolAddress((void**)&w1h, g_w1h);
    cudaGetSymbolAddress((void**)&w3h, g_w3h);
    cudaGetSymbolAddress((void**)&w2h, g_w2h);

    prep_kernel<<<dim3(4096, 4), 256>>>(w1, w1h, w3, w3h, w2, w2h,
                                        (long)NE * NI * DIM / 4,
                                        x, w_gate, out);
    sort_kernel<<<1, 256>>>();
    mma1_kernel<<<dim3(NI / 64, NE * (CAP / 128)), 256, 4 * STG1>>>();
    mma2_kernel<<<dim3(DIM / 128, NE * (CAP / 128)), 256, 4 * STG2>>>(out);
}

// round 17
// speedup vs baseline: 1.3149x; 1.3149x over previous
#include <cuda_runtime.h>
#include <cuda_fp16.h>
#include <math.h>
#include <stdint.h>

// Problem constants (fixed by the dataset)
#define T_TOK 2048
#define DIM   2048
#define NE    8
#define NI    2048
#define CAP   2048
#define SOFTCAP 30.0f

// ---------------- device scratch (no runtime allocation) ----------------
__device__ __half g_xh [(size_t)T_TOK * DIM];
__device__ __half g_w1h[(size_t)NE * NI * DIM];
__device__ __half g_w3h[(size_t)NE * NI * DIM];
__device__ __half g_w2h[(size_t)NE * DIM * NI];
__device__ __half g_hh [(size_t)NE * CAP * NI];     // GLU hidden, fp16
__device__ int    g_sel_token[NE * CAP];
__device__ float  g_sel_w[NE * CAP];
__device__ int    g_count[NE];
__device__ int    g_topk_idx[T_TOK * 2];
__device__ float  g_topk_w[T_TOK * 2];

// ---------------- helpers ----------------
__device__ __forceinline__ float gelu_exact(float v) {
    return 0.5f * v * (1.0f + erff(v * 0.70710678118654752440f));
}
__device__ __forceinline__ uint32_t smem_u32(const void* p) {
    uint32_t a;
    asm("{ .reg .u64 t; cvta.to.shared.u64 t, %1; cvt.u32.u64 %0, t; }" : "=r"(a) : "l"(p));
    return a;
}
__device__ __forceinline__ void cp16(uint32_t dst, const void* src) {
    asm volatile("cp.async.cg.shared.global [%0], [%1], 16;" :: "r"(dst), "l"(src) : "memory");
}
#define CP_COMMIT() asm volatile("cp.async.commit_group;" ::: "memory")

#define LDSM4(r0, r1, r2, r3, addr) \
    asm volatile("ldmatrix.sync.aligned.m8n8.x4.shared.b16 {%0,%1,%2,%3}, [%4];" \
                 : "=r"(r0), "=r"(r1), "=r"(r2), "=r"(r3) : "r"(addr))

#define MMA4(c, a, b0, b1) \
    asm volatile("mma.sync.aligned.m16n8k16.row.col.f32.f16.f16.f32 " \
                 "{%0,%1,%2,%3}, {%4,%5,%6,%7}, {%8,%9}, {%0,%1,%2,%3};" \
                 : "+f"((c)[0]), "+f"((c)[1]), "+f"((c)[2]), "+f"((c)[3]) \
                 : "r"((a)[0]), "r"((a)[1]), "r"((a)[2]), "r"((a)[3]), \
                   "r"(b0), "r"(b1))

// vector fp32 atomic add (no return): 8B-aligned address required.
__device__ __forceinline__ void red_add_v2(float* p, float a, float b) {
    asm volatile("red.global.add.v2.f32 [%0], {%1, %2};" :: "l"(p), "f"(a), "f"(b) : "memory");
}

// smem tile geometry: rows of 32 halves (64B) + 16B pad -> 80B row stride.
// conflict-free for both cp.async writes and ldmatrix reads.
#define ROWB 80

// ------ 1) fused: fp32->fp16 weight converts (y=0..2) + router (y=3) ------
__global__ void prep_kernel(const float* __restrict__ s0, __half* __restrict__ d0,
                            const float* __restrict__ s1, __half* __restrict__ d1,
                            const float* __restrict__ s2, __half* __restrict__ d2,
                            long n4,
                            const float* __restrict__ x,
                            const float* __restrict__ wg,
                            float* __restrict__ out) {
    const int tid = threadIdx.x;
    if (blockIdx.y < 3) {
        const float* src = (blockIdx.y == 0) ? s0 : (blockIdx.y == 1) ? s1 : s2;
        __half*      dst = (blockIdx.y == 0) ? d0 : (blockIdx.y == 1) ? d1 : d2;
        long i = (long)blockIdx.x * 256 + tid;
        const long stride = (long)gridDim.x * 256;
        for (; i < n4; i += stride) {
            float4 v = ((const float4*)src)[i];
            __half2 h0 = __floats2half2_rn(v.x, v.y);
            __half2 h1 = __floats2half2_rn(v.z, v.w);
            uint2 o;
            o.x = *(uint32_t*)&h0;
            o.y = *(uint32_t*)&h1;
            ((uint2*)dst)[i] = o;
        }
        return;
    }
    // ---- router branch ----
    const int t = blockIdx.x;
    if (t >= T_TOK) return;
    const float4* xr4 = (const float4*)(x + (size_t)t * DIM);
    const float4* wg4 = (const float4*)wg;

    // zero this token's output row (atomic-accumulation target for mma2)
    float4* orow = (float4*)(out + (size_t)t * DIM);
#pragma unroll
    for (int q = tid; q < DIM / 4; q += 256)
        orow[q] = make_float4(0.f, 0.f, 0.f, 0.f);

    float acc[NE];
#pragma unroll
    for (int e = 0; e < NE; e++) acc[e] = 0.f;
#pragma unroll
    for (int q = tid; q < DIM / 4; q += 256) {      // 2 trips
        float4 xv = xr4[q];
        __half2 h0 = __floats2half2_rn(xv.x, xv.y);
        __half2 h1 = __floats2half2_rn(xv.z, xv.w);
        uint2 o; o.x = *(uint32_t*)&h0; o.y = *(uint32_t*)&h1;
        ((uint2*)(g_xh + (size_t)t * DIM))[q] = o;  // fused convert
#pragma unroll
        for (int e = 0; e < NE; e++) {
            float4 w = wg4[e * (DIM / 4) + q];
            acc[e] += xv.x * w.x + xv.y * w.y + xv.z * w.z + xv.w * w.w;
        }
    }

    __shared__ float sh[NE][256];
#pragma unroll
    for (int e = 0; e < NE; e++) sh[e][tid] = acc[e];
    __syncthreads();
    for (int s = 128; s > 0; s >>= 1) {
        if (tid < s) {
#pragma unroll
            for (int e = 0; e < NE; e++) sh[e][tid] += sh[e][tid + s];
        }
        __syncthreads();
    }

    if (tid == 0) {
        float l[NE];
        float mx = -1e30f;
#pragma unroll
        for (int e = 0; e < NE; e++) {
            l[e] = SOFTCAP * tanhf(sh[e][0] / SOFTCAP);
            mx = fmaxf(mx, l[e]);
        }
        float sum = 0.f;
#pragma unroll
        for (int e = 0; e < NE; e++) { l[e] = expf(l[e] - mx); sum += l[e]; }
        float inv = 1.f / sum;
        int i0 = 0;
#pragma unroll
        for (int e = 1; e < NE; e++) if (l[e] > l[i0]) i0 = e;
        int i1 = (i0 == 0) ? 1 : 0;
#pragma unroll
        for (int e = 0; e < NE; e++) {
            if (e == i0) continue;
            if (l[e] > l[i1]) i1 = e;
        }
        g_topk_idx[t * 2 + 0] = i0; g_topk_w[t * 2 + 0] = l[i0] * inv;
        g_topk_idx[t * 2 + 1] = i1; g_topk_w[t * 2 + 1] = l[i1] * inv;
    }
}

// ---------------- 2) Deterministic counting sort by expert ----------------
__global__ void sort_kernel() {
    const int wid  = threadIdx.x >> 5;
    const int lane = threadIdx.x & 31;
    if (wid >= NE) return;
    int running = 0;
    for (int base = 0; base < T_TOK * 2; base += 32) {
        const int s  = base + lane;
        const int ex = g_topk_idx[s];
        const bool p = (ex == wid);
        const unsigned m = __ballot_sync(0xffffffffu, p);
        if (p) {
            const int rank = running + __popc(m & ((1u << lane) - 1u));
            const int pos  = wid * CAP + rank;
            g_sel_token[pos] = s >> 1;
            g_sel_w[pos]     = g_topk_w[s];
        }
        running += __popc(m);
    }
    if (lane == 0) g_count[wid] = running;
}

// ---------------- 3) GEMM1: h = gelu(Xsel W1^T) * (Xsel W3^T) ----------------
// CTA 128(M) x 64(N), dual B. Double-buffered k64 pairs over 4 x k32 buffers
// (2 pair-buffers of 40960 B, 81920 B total -> 2 CTAs/SM). One wait_group +
// one __syncthreads per k64 (32 total, half of R13). Loads for pair i+1 are
// issued BEFORE computing pair i: write buffer (i+1)&1 is disjoint from read
// buffer i&1, and cross-warp visibility comes from next iteration's wait+sync.
#define STG1 20480   // one k32 subtile: A 128*80 + B1 64*80 + B3 64*80

__global__ __launch_bounds__(256) void mma1_kernel() {
    const int e    = blockIdx.y >> 4;
    const int mt   = blockIdx.y & 15;
    const int row0 = mt * 128;
    const int cnt  = g_count[e];
    if (row0 >= cnt) return;
    const int n0 = blockIdx.x * 64;

    extern __shared__ char dsm[];
    __shared__ int tok[128];

    const int tid  = threadIdx.x;
    const int wid  = tid >> 5;
    const int lane = tid & 31;

    if (tid < 128) {
        const int r = row0 + tid;
        tok[tid] = (r < cnt) ? g_sel_token[e * CAP + r] : 0;
    }
    __syncthreads();

    const uint32_t dyn0 = smem_u32(dsm);

    const int seg = tid & 3;        // k segment (8 halves)
    const int r64 = tid >> 2;       // 0..63
    const __half* a0src = g_xh  + (size_t)tok[r64]      * DIM + seg * 8;
    const __half* a1src = g_xh  + (size_t)tok[r64 + 64] * DIM + seg * 8;
    const __half* b1src = g_w1h + ((size_t)e * NI + n0 + r64) * DIM + seg * 8;
    const __half* b3src = g_w3h + ((size_t)e * NI + n0 + r64) * DIM + seg * 8;
    const uint32_t dA0 = (uint32_t)(r64 * ROWB + seg * 16);
    const uint32_t dA1 = (uint32_t)((r64 + 64) * ROWB + seg * 16);

    // one pair = 2 k32 subtiles; pair p lives in buffer (p&1)
    auto load_pair = [&](int p) {
        const uint32_t pb = dyn0 + (uint32_t)(p & 1) * (2 * STG1);
        const int kb = p * 64;
#pragma unroll
        for (int u = 0; u < 2; u++) {
            const uint32_t b = pb + u * STG1;
            const int ko = kb + u * 32;
            cp16(b + dA0, a0src + ko);
            cp16(b + dA1, a1src + ko);
            cp16(b + 10240 + dA0, b1src + ko);
            cp16(b + 15360 + dA0, b3src + ko);
        }
        CP_COMMIT();
    };
    load_pair(0);

    const int wm = wid & 1, wn = wid >> 1;
    float c1[4][2][4], c3[4][2][4];
#pragma unroll
    for (int mf = 0; mf < 4; mf++)
#pragma unroll
        for (int nf = 0; nf < 2; nf++)
#pragma unroll
            for (int k = 0; k < 4; k++) { c1[mf][nf][k] = 0.f; c3[mf][nf][k] = 0.f; }

    const uint32_t lrow = (uint32_t)((lane & 15) * ROWB + (lane >> 4) * 16);

    for (int i = 0; i < 32; i++) {
        asm volatile("cp.async.wait_group 0;" ::: "memory");
        __syncthreads();
        if (i + 1 < 32) load_pair(i + 1);          // prefetch next pair first

        const uint32_t pb = dyn0 + (uint32_t)(i & 1) * (2 * STG1);
#pragma unroll
        for (int u = 0; u < 2; u++) {
            const uint32_t sb  = pb + u * STG1;
            const uint32_t Ab  = sb + (uint32_t)(wm * 64 * ROWB) + lrow;
            const uint32_t B1b = sb + 10240 + (uint32_t)(wn * 16 * ROWB) + lrow;
            const uint32_t B3b = sb + 15360 + (uint32_t)(wn * 16 * ROWB) + lrow;
#pragma unroll
            for (int kk = 0; kk < 2; kk++) {
                uint32_t p1[4], p3[4];
                LDSM4(p1[0], p1[1], p1[2], p1[3], B1b + kk * 32);
                LDSM4(p3[0], p3[1], p3[2], p3[3], B3b + kk * 32);
#pragma unroll
                for (int mf = 0; mf < 4; mf++) {
                    uint32_t a[4];
                    LDSM4(a[0], a[1], a[2], a[3], Ab + mf * (16 * ROWB) + kk * 32);
                    MMA4(c1[mf][0], a, p1[0], p1[2]);
                    MMA4(c1[mf][1], a, p1[1], p1[3]);
                    MMA4(c3[mf][0], a, p3[0], p3[2]);
                    MMA4(c3[mf][1], a, p3[1], p3[3]);
                }
            }
        }
    }

    // epilogue: h = gelu(a) * b -> fp16
#pragma unroll
    for (int mf = 0; mf < 4; mf++) {
        const int rb = row0 + wm * 64 + mf * 16 + (lane >> 2);
#pragma unroll
        for (int nf = 0; nf < 2; nf++) {
            const int col = n0 + wn * 16 + nf * 8 + (lane & 3) * 2;
            if (rb < cnt) {
                __half2 h = __floats2half2_rn(
                    gelu_exact(c1[mf][nf][0]) * c3[mf][nf][0],
                    gelu_exact(c1[mf][nf][1]) * c3[mf][nf][1]);
                *(__half2*)(g_hh + ((size_t)(e * CAP) + rb) * NI + col) = h;
            }
            if (rb + 8 < cnt) {
                __half2 h = __floats2half2_rn(
                    gelu_exact(c1[mf][nf][2]) * c3[mf][nf][2],
                    gelu_exact(c1[mf][nf][3]) * c3[mf][nf][3]);
                *(__half2*)(g_hh + ((size_t)(e * CAP) + rb + 8) * NI + col) = h;
            }
        }
    }
}

// ---------------- 4) GEMM2: out[token] += sel_w * (h W2^T) (vector RED) ---
// CTA 128(M) x 128(N). Same double-buffered k64 pair pipeline.
#define STG2 20480   // one k32 subtile: A 128*80 + B 128*80

__global__ __launch_bounds__(256) void mma2_kernel(float* __restrict__ out) {
    const int e    = blockIdx.y >> 4;
    const int mt   = blockIdx.y & 15;
    const int row0 = mt * 128;
    const int cnt  = g_count[e];
    if (row0 >= cnt) return;
    const int n0 = blockIdx.x * 128;

    extern __shared__ char dsm[];
    __shared__ int tok[128];

    const int tid  = threadIdx.x;
    const int wid  = tid >> 5;
    const int lane = tid & 31;

    if (tid < 128) {
        const int r = row0 + tid;
        tok[tid] = (r < cnt) ? g_sel_token[e * CAP + r] : 0;
    }
    __syncthreads();

    const uint32_t dyn0 = smem_u32(dsm);

    const int seg = tid & 3;
    const int r64 = tid >> 2;
    const __half* a0src = g_hh  + ((size_t)(e * CAP) + row0 + r64)      * NI + seg * 8;
    const __half* a1src = g_hh  + ((size_t)(e * CAP) + row0 + r64 + 64) * NI + seg * 8;
    const __half* b0src = g_w2h + ((size_t)e * DIM + n0 + r64)      * NI + seg * 8;
    const __half* b1src = g_w2h + ((size_t)e * DIM + n0 + r64 + 64) * NI + seg * 8;
    const uint32_t d0 = (uint32_t)(r64 * ROWB + seg * 16);
    const uint32_t d1 = (uint32_t)((r64 + 64) * ROWB + seg * 16);

    auto load_pair = [&](int p) {
        const uint32_t pb = dyn0 + (uint32_t)(p & 1) * (2 * STG2);
        const int kb = p * 64;
#pragma unroll
        for (int u = 0; u < 2; u++) {
            const uint32_t b = pb + u * STG2;
            const int ko = kb + u * 32;
            cp16(b + d0, a0src + ko);
            cp16(b + d1, a1src + ko);
            cp16(b + 10240 + d0, b0src + ko);
            cp16(b + 10240 + d1, b1src + ko);
        }
        CP_COMMIT();
    };
    load_pair(0);

    const int wm = wid & 1, wn = wid >> 1;
    float c[4][4][4];
#pragma unroll
    for (int mf = 0; mf < 4; mf++)
#pragma unroll
        for (int nf = 0; nf < 4; nf++)
#pragma unroll
            for (int k = 0; k < 4; k++) c[mf][nf][k] = 0.f;

    const uint32_t lrow = (uint32_t)((lane & 15) * ROWB + (lane >> 4) * 16);

    for (int i = 0; i < 32; i++) {
        asm volatile("cp.async.wait_group 0;" ::: "memory");
        __syncthreads();
        if (i + 1 < 32) load_pair(i + 1);

        const uint32_t pb = dyn0 + (uint32_t)(i & 1) * (2 * STG2);
#pragma unroll
        for (int u = 0; u < 2; u++) {
            const uint32_t sb = pb + u * STG2;
            const uint32_t Ab = sb + (uint32_t)(wm * 64 * ROWB) + lrow;
            const uint32_t Bb = sb + 10240 + (uint32_t)(wn * 32 * ROWB) + lrow;
#pragma unroll
            for (int kk = 0; kk < 2; kk++) {
                uint32_t bb0[4], bb1v[4];
                LDSM4(bb0[0], bb0[1], bb0[2], bb0[3], Bb + kk * 32);
                LDSM4(bb1v[0], bb1v[1], bb1v[2], bb1v[3], Bb + 16 * ROWB + kk * 32);
#pragma unroll
                for (int mf = 0; mf < 4; mf++) {
                    uint32_t a[4];
                    LDSM4(a[0], a[1], a[2], a[3], Ab + mf * (16 * ROWB) + kk * 32);
                    MMA4(c[mf][0], a, bb0[0], bb0[2]);
                    MMA4(c[mf][1], a, bb0[1], bb0[3]);
                    MMA4(c[mf][2], a, bb1v[0], bb1v[2]);
                    MMA4(c[mf][3], a, bb1v[1], bb1v[3]);
                }
            }
        }
    }

    // epilogue: scale by routing weight, vector-RED into out[token]
#pragma unroll
    for (int mf = 0; mf < 4; mf++) {
        const int rb = row0 + wm * 64 + mf * 16 + (lane >> 2);
        const float w0 = (rb < cnt)     ? g_sel_w[e * CAP + rb]     : 0.f;
        const float w1 = (rb + 8 < cnt) ? g_sel_w[e * CAP + rb + 8] : 0.f;
        const int t0 = tok[rb - row0 < 128 ? rb - row0 : 0];
        const int t1 = tok[(rb + 8 - row0) < 128 ? (rb + 8 - row0) : 0];
#pragma unroll
        for (int nf = 0; nf < 4; nf++) {
            const int col = n0 + wn * 32 + nf * 8 + (lane & 3) * 2;   // even -> 8B aligned
            if (rb < cnt)
                red_add_v2(out + (size_t)t0 * DIM + col,
                           c[mf][nf][0] * w0, c[mf][nf][1] * w0);
            if (rb + 8 < cnt)
                red_add_v2(out + (size_t)t1 * DIM + col,
                           c[mf][nf][2] * w1, c[mf][nf][3] * w1);
        }
    }
}

// ---------------- launch ----------------
extern "C" void kernel_launch(void* const* d_in, const int* in_sizes, int n_in,
                              void* d_out, int out_size) {
    const float* x      = (const float*)d_in[0];
    const float* w_gate = (const float*)d_in[1];
    const float* w1     = (const float*)d_in[2];
    const float* w3     = (const float*)d_in[3];
    const float* w2     = (const float*)d_in[4];
    float* out = (float*)d_out;
    (void)in_sizes; (void)n_in; (void)out_size;

    cudaFuncSetAttribute(mma1_kernel, cudaFuncAttributeMaxDynamicSharedMemorySize, 4 * STG1);
    cudaFuncSetAttribute(mma2_kernel, cudaFuncAttributeMaxDynamicSharedMemorySize, 4 * STG2);

    __half *w1h, *w3h, *w2h;
    cudaGetSymbolAddress((void**)&w1h, g_w1h);
    cudaGetSymbolAddress((void**)&w3h, g_w3h);
    cudaGetSymbolAddress((void**)&w2h, g_w2h);

    prep_kernel<<<dim3(4096, 4), 256>>>(w1, w1h, w3, w3h, w2, w2h,
                                        (long)NE * NI * DIM / 4,
                                        x, w_gate, out);
    sort_kernel<<<1, 256>>>();
    mma1_kernel<<<dim3(NI / 64, NE * (CAP / 128)), 256, 4 * STG1>>>();
    mma2_kernel<<<dim3(DIM / 128, NE * (CAP / 128)), 256, 4 * STG2>>>(out);
}